// round 2
// baseline (speedup 1.0000x reference)
#include <cuda_runtime.h>

// Problem: loss = mean(|preds*mask - targets|) + 0.1 * mean((pd - td)^2)
//   mask = (targets != 0), bones i -> (i+1) % 50, directions = diff/(||diff||+1e-8)
// Shapes: preds/targets [128, 1024, 150] fp32; scalar fp32 output.

#define ROW_ELEMS 150
#define N_BONES 50
#define ROWS_PER_BLOCK 16
#define THREADS 256
#define TOTAL_ROWS (128 * 1024)
#define NUM_BLOCKS (TOTAL_ROWS / ROWS_PER_BLOCK)   // 8192
#define BLOCK_ELEMS (ROWS_PER_BLOCK * ROW_ELEMS)   // 2400
#define BLOCK_VEC4 (BLOCK_ELEMS / 4)               // 600

__device__ float2 g_partials[NUM_BLOCKS];

__global__ __launch_bounds__(THREADS) void loss_main(
    const float* __restrict__ preds,
    const float* __restrict__ targets)
{
    __shared__ float p_s[BLOCK_ELEMS];
    __shared__ float t_s[BLOCK_ELEMS];

    const int tid = threadIdx.x;
    const long long base = (long long)blockIdx.x * BLOCK_ELEMS;

    // Coalesced float4 staging of 16 contiguous rows of both tensors.
    const float4* __restrict__ p4 = (const float4*)(preds + base);
    const float4* __restrict__ t4 = (const float4*)(targets + base);
    float4* p_s4 = (float4*)p_s;
    float4* t_s4 = (float4*)t_s;
    #pragma unroll
    for (int k = tid; k < BLOCK_VEC4; k += THREADS) {
        p_s4[k] = p4[k];
        t_s4[k] = t4[k];
    }
    __syncthreads();

    float l1 = 0.0f;
    float mse = 0.0f;

    // ---- L1 term: mean(|preds*mask - targets*mask|); targets*mask == targets ----
    #pragma unroll 2
    for (int k = tid; k < BLOCK_ELEMS; k += THREADS) {
        float t = t_s[k];
        float p = p_s[k];
        float pm = (t != 0.0f) ? p : 0.0f;
        l1 += fabsf(pm - t);
    }

    // ---- Bone direction MSE term ----
    // 16 rows * 50 bones = 800 tasks
    for (int task = tid; task < ROWS_PER_BLOCK * N_BONES; task += THREADS) {
        int r = task / N_BONES;
        int i = task - r * N_BONES;
        int j1 = (i + 1 == N_BONES) ? 0 : (i + 1);
        const float* __restrict__ pr = p_s + r * ROW_ELEMS;
        const float* __restrict__ tr = t_s + r * ROW_ELEMS;

        float pdv[3], tdv[3], m[3];
        float pl2 = 0.0f, tl2 = 0.0f;
        #pragma unroll
        for (int d = 0; d < 3; d++) {
            float t0 = tr[i * 3 + d];
            float t1 = tr[j1 * 3 + d];
            float p0 = pr[i * 3 + d];
            float p1 = pr[j1 * 3 + d];
            float pm0 = (t0 != 0.0f) ? p0 : 0.0f;
            float pm1 = (t1 != 0.0f) ? p1 : 0.0f;
            float pdiff = pm0 - pm1;
            float tdiff = t0 - t1;      // t already equals t*mask
            pdv[d] = pdiff;
            tdv[d] = tdiff;
            m[d] = (t0 != 0.0f) ? 1.0f : 0.0f;  // loss_mask at element i*3+d
            pl2 += pdiff * pdiff;
            tl2 += tdiff * tdiff;
        }
        float pinv = 1.0f / (sqrtf(pl2) + 1e-8f);
        float tinv = 1.0f / (sqrtf(tl2) + 1e-8f);
        #pragma unroll
        for (int d = 0; d < 3; d++) {
            float x = (pdv[d] * pinv - tdv[d] * tinv) * m[d];
            mse += x * x;
        }
    }

    // ---- deterministic block reduction ----
    __shared__ float s_l1[THREADS];
    __shared__ float s_mse[THREADS];
    s_l1[tid] = l1;
    s_mse[tid] = mse;
    __syncthreads();
    #pragma unroll
    for (int s = THREADS / 2; s > 0; s >>= 1) {
        if (tid < s) {
            s_l1[tid] += s_l1[tid + s];
            s_mse[tid] += s_mse[tid + s];
        }
        __syncthreads();
    }
    if (tid == 0) {
        g_partials[blockIdx.x] = make_float2(s_l1[0], s_mse[0]);
    }
}

__global__ __launch_bounds__(256) void loss_reduce(float* __restrict__ out)
{
    __shared__ double s_l1[256];
    __shared__ double s_mse[256];
    const int tid = threadIdx.x;
    double l1 = 0.0, mse = 0.0;
    for (int k = tid; k < NUM_BLOCKS; k += 256) {
        float2 v = g_partials[k];
        l1 += (double)v.x;
        mse += (double)v.y;
    }
    s_l1[tid] = l1;
    s_mse[tid] = mse;
    __syncthreads();
    #pragma unroll
    for (int s = 128; s > 0; s >>= 1) {
        if (tid < s) {
            s_l1[tid] += s_l1[tid + s];
            s_mse[tid] += s_mse[tid + s];
        }
        __syncthreads();
    }
    if (tid == 0) {
        const double TOT = (double)TOTAL_ROWS * (double)ROW_ELEMS;  // 19,660,800
        out[0] = (float)(s_l1[0] / TOT + 0.1 * (s_mse[0] / TOT));
    }
}

extern "C" void kernel_launch(void* const* d_in, const int* in_sizes, int n_in,
                              void* d_out, int out_size)
{
    const float* preds   = (const float*)d_in[0];
    const float* targets = (const float*)d_in[1];
    float* out = (float*)d_out;

    loss_main<<<NUM_BLOCKS, THREADS>>>(preds, targets);
    loss_reduce<<<1, 256>>>(out);
}

// round 5
// speedup vs baseline: 1.2699x; 1.2699x over previous
#include <cuda_runtime.h>

// loss = mean(|preds*mask - targets|) + 0.1 * mean((pd - td)^2)
//   mask = (targets != 0), bones i -> (i+1) % 50, dir = diff/(||diff||+1e-8)
// preds/targets: [128, 1024, 150] fp32; scalar fp32 output.

#define ROW_ELEMS 150
#define N_BONES 50
#define ROWS_PER_TILE 16
#define THREADS 256
#define TOTAL_ROWS (128 * 1024)
#define NUM_TILES (TOTAL_ROWS / ROWS_PER_TILE)     // 8192
#define TILE_ELEMS (ROWS_PER_TILE * ROW_ELEMS)     // 2400
#define TILE_VEC4 (TILE_ELEMS / 4)                 // 600
#define LAUNCH_BLOCKS (148 * 8)                    // 1184 persistent blocks

__device__ float2 g_partials[LAUNCH_BLOCKS];

__global__ __launch_bounds__(THREADS) void loss_main(
    const float* __restrict__ preds,
    const float* __restrict__ targets)
{
    __shared__ float pm_s[TILE_ELEMS];   // masked preds
    __shared__ float t_s[TILE_ELEMS];    // targets (== targets*mask)

    const int tid = threadIdx.x;

    float l1 = 0.0f;
    float mse = 0.0f;

    for (int tile = blockIdx.x; tile < NUM_TILES; tile += LAUNCH_BLOCKS) {
        const long long base = (long long)tile * TILE_ELEMS;
        const float4* __restrict__ p4 = (const float4*)(preds + base);
        const float4* __restrict__ t4 = (const float4*)(targets + base);
        float4* pm_s4 = (float4*)pm_s;
        float4* t_s4 = (float4*)t_s;

        // Stage + fused L1: compute |pm - t| from registers, store masked p.
        #pragma unroll
        for (int k = tid; k < TILE_VEC4; k += THREADS) {
            float4 p = p4[k];
            float4 t = t4[k];
            float4 pm;
            pm.x = (t.x != 0.0f) ? p.x : 0.0f;
            pm.y = (t.y != 0.0f) ? p.y : 0.0f;
            pm.z = (t.z != 0.0f) ? p.z : 0.0f;
            pm.w = (t.w != 0.0f) ? p.w : 0.0f;
            l1 += fabsf(pm.x - t.x) + fabsf(pm.y - t.y)
                + fabsf(pm.z - t.z) + fabsf(pm.w - t.w);
            pm_s4[k] = pm;
            t_s4[k] = t;
        }
        __syncthreads();

        // Bone direction MSE: 16 rows * 50 bones = 800 tasks.
        #pragma unroll 2
        for (int task = tid; task < ROWS_PER_TILE * N_BONES; task += THREADS) {
            int r = task / N_BONES;
            int i = task - r * N_BONES;
            int j1 = (i + 1 == N_BONES) ? 0 : (i + 1);
            const float* __restrict__ pr = pm_s + r * ROW_ELEMS;
            const float* __restrict__ tr = t_s + r * ROW_ELEMS;

            float pdv[3], tdv[3], m[3];
            float pl2 = 0.0f, tl2 = 0.0f;
            #pragma unroll
            for (int d = 0; d < 3; d++) {
                float t0 = tr[i * 3 + d];
                float t1 = tr[j1 * 3 + d];
                float pdiff = pr[i * 3 + d] - pr[j1 * 3 + d];  // already masked
                float tdiff = t0 - t1;
                pdv[d] = pdiff;
                tdv[d] = tdiff;
                m[d] = (t0 != 0.0f) ? 1.0f : 0.0f;  // loss_mask at element i*3+d
                pl2 += pdiff * pdiff;
                tl2 += tdiff * tdiff;
            }
            float pinv = 1.0f / (sqrtf(pl2) + 1e-8f);
            float tinv = 1.0f / (sqrtf(tl2) + 1e-8f);
            #pragma unroll
            for (int d = 0; d < 3; d++) {
                float x = (pdv[d] * pinv - tdv[d] * tinv) * m[d];
                mse += x * x;
            }
        }
        __syncthreads();   // SMEM reuse guard for next tile
    }

    // ---- deterministic block reduction (once per persistent block) ----
    __shared__ float s_l1[THREADS];
    __shared__ float s_mse[THREADS];
    s_l1[tid] = l1;
    s_mse[tid] = mse;
    __syncthreads();
    #pragma unroll
    for (int s = THREADS / 2; s > 0; s >>= 1) {
        if (tid < s) {
            s_l1[tid] += s_l1[tid + s];
            s_mse[tid] += s_mse[tid + s];
        }
        __syncthreads();
    }
    if (tid == 0) {
        g_partials[blockIdx.x] = make_float2(s_l1[0], s_mse[0]);
    }
}

__global__ __launch_bounds__(256) void loss_reduce(float* __restrict__ out)
{
    __shared__ double s_l1[256];
    __shared__ double s_mse[256];
    const int tid = threadIdx.x;
    double l1 = 0.0, mse = 0.0;
    #pragma unroll
    for (int k = tid; k < LAUNCH_BLOCKS; k += 256) {
        float2 v = g_partials[k];
        l1 += (double)v.x;
        mse += (double)v.y;
    }
    s_l1[tid] = l1;
    s_mse[tid] = mse;
    __syncthreads();
    #pragma unroll
    for (int s = 128; s > 0; s >>= 1) {
        if (tid < s) {
            s_l1[tid] += s_l1[tid + s];
            s_mse[tid] += s_mse[tid + s];
        }
        __syncthreads();
    }
    if (tid == 0) {
        const double TOT = (double)TOTAL_ROWS * (double)ROW_ELEMS;  // 19,660,800
        out[0] = (float)(s_l1[0] / TOT + 0.1 * (s_mse[0] / TOT));
    }
}

extern "C" void kernel_launch(void* const* d_in, const int* in_sizes, int n_in,
                              void* d_out, int out_size)
{
    const float* preds   = (const float*)d_in[0];
    const float* targets = (const float*)d_in[1];
    float* out = (float*)d_out;

    loss_main<<<LAUNCH_BLOCKS, THREADS>>>(preds, targets);
    loss_reduce<<<1, 256>>>(out);
}

// round 6
// speedup vs baseline: 1.3857x; 1.0913x over previous
#include <cuda_runtime.h>

// loss = mean(|preds*mask - targets|) + 0.1 * mean((pd - td)^2)
//   mask = (targets != 0), bones i -> (i+1) % 50, dir = diff/(||diff||+1e-8)
// preds/targets: [128, 1024, 150] fp32; scalar fp32 output.

#define ROW_ELEMS 150
#define N_BONES 50
#define TOTAL_ROWS (128 * 1024)
#define THREADS 256
#define WARPS_PER_BLOCK (THREADS / 32)
#define LAUNCH_BLOCKS (148 * 8)                      // 1184
#define TOTAL_WARPS (LAUNCH_BLOCKS * WARPS_PER_BLOCK) // 9472
#define ROWS_PER_WTILE 2
#define WTILE_ELEMS (ROWS_PER_WTILE * ROW_ELEMS)     // 300 floats (75 float4)
#define WTILE_VEC4 (WTILE_ELEMS / 4)                 // 75
#define NUM_WTILES (TOTAL_ROWS / ROWS_PER_WTILE)     // 65536

__device__ float2 g_partials[LAUNCH_BLOCKS];
__device__ unsigned int g_count;                     // zero-init; self-resets

__global__ __launch_bounds__(THREADS) void loss_fused(
    const float* __restrict__ preds,
    const float* __restrict__ targets,
    float* __restrict__ out)
{
    // Per-warp private SMEM slices: masked preds + targets, 300 floats each.
    __shared__ float pm_sh[WARPS_PER_BLOCK][WTILE_ELEMS];
    __shared__ float t_sh[WARPS_PER_BLOCK][WTILE_ELEMS];

    const int tid = threadIdx.x;
    const int wid = tid >> 5;
    const int lane = tid & 31;
    const int gwarp = blockIdx.x * WARPS_PER_BLOCK + wid;

    float* pm_s = pm_sh[wid];
    float* t_s = t_sh[wid];
    float4* pm_s4 = (float4*)pm_s;
    float4* t_s4 = (float4*)t_s;

    float l1 = 0.0f;
    float mse = 0.0f;

    for (int wt = gwarp; wt < NUM_WTILES; wt += TOTAL_WARPS) {
        const long long base4 = (long long)wt * WTILE_VEC4;
        const float4* __restrict__ p4 = (const float4*)preds + base4;
        const float4* __restrict__ t4 = (const float4*)targets + base4;

        // Front-batched loads: 75 float4 per tensor over 32 lanes (2-3 each).
        float4 pA, pB, pC, tA, tB, tC;
        pA = p4[lane];        tA = t4[lane];
        pB = p4[lane + 32];   tB = t4[lane + 32];
        const bool hasC = (lane < WTILE_VEC4 - 64);   // lanes 0..10
        if (hasC) { pC = p4[lane + 64]; tC = t4[lane + 64]; }

        __syncwarp();   // SMEM reuse guard: prior bone pass done before overwrite

        // Mask + L1 + SMEM store (fused).
        {
            float4 pm;
            pm.x = (tA.x != 0.0f) ? pA.x : 0.0f;
            pm.y = (tA.y != 0.0f) ? pA.y : 0.0f;
            pm.z = (tA.z != 0.0f) ? pA.z : 0.0f;
            pm.w = (tA.w != 0.0f) ? pA.w : 0.0f;
            l1 += fabsf(pm.x - tA.x) + fabsf(pm.y - tA.y)
                + fabsf(pm.z - tA.z) + fabsf(pm.w - tA.w);
            pm_s4[lane] = pm;  t_s4[lane] = tA;

            pm.x = (tB.x != 0.0f) ? pB.x : 0.0f;
            pm.y = (tB.y != 0.0f) ? pB.y : 0.0f;
            pm.z = (tB.z != 0.0f) ? pB.z : 0.0f;
            pm.w = (tB.w != 0.0f) ? pB.w : 0.0f;
            l1 += fabsf(pm.x - tB.x) + fabsf(pm.y - tB.y)
                + fabsf(pm.z - tB.z) + fabsf(pm.w - tB.w);
            pm_s4[lane + 32] = pm;  t_s4[lane + 32] = tB;

            if (hasC) {
                pm.x = (tC.x != 0.0f) ? pC.x : 0.0f;
                pm.y = (tC.y != 0.0f) ? pC.y : 0.0f;
                pm.z = (tC.z != 0.0f) ? pC.z : 0.0f;
                pm.w = (tC.w != 0.0f) ? pC.w : 0.0f;
                l1 += fabsf(pm.x - tC.x) + fabsf(pm.y - tC.y)
                    + fabsf(pm.z - tC.z) + fabsf(pm.w - tC.w);
                pm_s4[lane + 64] = pm;  t_s4[lane + 64] = tC;
            }
        }
        __syncwarp();

        // Bone pass: 2 rows * 50 bones = 100 tasks over 32 lanes.
        #pragma unroll
        for (int tk = 0; tk < 4; tk++) {
            int task = lane + tk * 32;
            if (task >= ROWS_PER_WTILE * N_BONES) break;
            int r = (task >= N_BONES) ? 1 : 0;
            int i = task - r * N_BONES;
            int j1 = (i + 1 == N_BONES) ? 0 : (i + 1);
            const float* __restrict__ pr = pm_s + r * ROW_ELEMS;
            const float* __restrict__ tr = t_s + r * ROW_ELEMS;

            float pdv[3], tdv[3], m[3];
            float pl2 = 0.0f, tl2 = 0.0f;
            #pragma unroll
            for (int d = 0; d < 3; d++) {
                float t0 = tr[i * 3 + d];
                float t1 = tr[j1 * 3 + d];
                float pdiff = pr[i * 3 + d] - pr[j1 * 3 + d];  // already masked
                float tdiff = t0 - t1;
                pdv[d] = pdiff;
                tdv[d] = tdiff;
                m[d] = (t0 != 0.0f) ? 1.0f : 0.0f;
                pl2 += pdiff * pdiff;
                tl2 += tdiff * tdiff;
            }
            float pinv = __fdividef(1.0f, sqrtf(pl2) + 1e-8f);
            float tinv = __fdividef(1.0f, sqrtf(tl2) + 1e-8f);
            #pragma unroll
            for (int d = 0; d < 3; d++) {
                float x = (pdv[d] * pinv - tdv[d] * tinv) * m[d];
                mse += x * x;
            }
        }
    }

    // ---- deterministic block reduction ----
    __shared__ float s_l1[THREADS];
    __shared__ float s_mse[THREADS];
    s_l1[tid] = l1;
    s_mse[tid] = mse;
    __syncthreads();
    #pragma unroll
    for (int s = THREADS / 2; s > 0; s >>= 1) {
        if (tid < s) {
            s_l1[tid] += s_l1[tid + s];
            s_mse[tid] += s_mse[tid + s];
        }
        __syncthreads();
    }

    // ---- last-arriving block does the final reduction (fixed order) ----
    __shared__ bool s_last;
    if (tid == 0) {
        g_partials[blockIdx.x] = make_float2(s_l1[0], s_mse[0]);
        __threadfence();
        unsigned int v = atomicAdd(&g_count, 1u);
        s_last = (v == LAUNCH_BLOCKS - 1);
    }
    __syncthreads();

    if (s_last) {
        __shared__ double d_l1[THREADS];
        __shared__ double d_mse[THREADS];
        double a = 0.0, b = 0.0;
        #pragma unroll
        for (int k = tid; k < LAUNCH_BLOCKS; k += THREADS) {
            float2 v = __ldcg(&g_partials[k]);
            a += (double)v.x;
            b += (double)v.y;
        }
        d_l1[tid] = a;
        d_mse[tid] = b;
        __syncthreads();
        #pragma unroll
        for (int s = THREADS / 2; s > 0; s >>= 1) {
            if (tid < s) {
                d_l1[tid] += d_l1[tid + s];
                d_mse[tid] += d_mse[tid + s];
            }
            __syncthreads();
        }
        if (tid == 0) {
            const double TOT = (double)TOTAL_ROWS * (double)ROW_ELEMS;
            out[0] = (float)(d_l1[0] / TOT + 0.1 * (d_mse[0] / TOT));
            g_count = 0;   // reset for next graph replay
        }
    }
}

extern "C" void kernel_launch(void* const* d_in, const int* in_sizes, int n_in,
                              void* d_out, int out_size)
{
    const float* preds   = (const float*)d_in[0];
    const float* targets = (const float*)d_in[1];
    float* out = (float*)d_out;

    loss_fused<<<LAUNCH_BLOCKS, THREADS>>>(preds, targets, out);
}

// round 7
// speedup vs baseline: 1.3943x; 1.0062x over previous
#include <cuda_runtime.h>

// loss = mean(|preds*mask - targets|) + 0.1 * mean((pd - td)^2)
//   mask = (targets != 0), bones i -> (i+1) % 50, dir = diff/(||diff||+1e-8)
// preds/targets: [128, 1024, 150] fp32; scalar fp32 output.

#define ROW_ELEMS 150
#define N_BONES 50
#define TOTAL_ROWS (128 * 1024)
#define THREADS 256
#define WARPS_PER_BLOCK (THREADS / 32)
#define BLOCKS_PER_SM 6
#define LAUNCH_BLOCKS (148 * BLOCKS_PER_SM)          // 888 — all resident, one wave
#define TOTAL_WARPS (LAUNCH_BLOCKS * WARPS_PER_BLOCK) // 7104
#define ROWS_PER_WTILE 2
#define WTILE_ELEMS (ROWS_PER_WTILE * ROW_ELEMS)     // 300 floats (75 float4)
#define WTILE_VEC4 (WTILE_ELEMS / 4)                 // 75
#define NUM_WTILES (TOTAL_ROWS / ROWS_PER_WTILE)     // 65536

__device__ float2 g_partials[LAUNCH_BLOCKS];
__device__ unsigned int g_count;                     // zero-init; self-resets

__global__ __launch_bounds__(THREADS, BLOCKS_PER_SM) void loss_fused(
    const float* __restrict__ preds,
    const float* __restrict__ targets,
    float* __restrict__ out)
{
    // Per-warp private SMEM slices: masked preds + targets, 300 floats each.
    __shared__ float pm_sh[WARPS_PER_BLOCK][WTILE_ELEMS];
    __shared__ float t_sh[WARPS_PER_BLOCK][WTILE_ELEMS];

    const int tid = threadIdx.x;
    const int wid = tid >> 5;
    const int lane = tid & 31;
    const int gwarp = blockIdx.x * WARPS_PER_BLOCK + wid;

    float* pm_s = pm_sh[wid];
    float* t_s = t_sh[wid];
    float4* pm_s4 = (float4*)pm_s;
    float4* t_s4 = (float4*)t_s;

    float l1 = 0.0f;
    float mse = 0.0f;

    for (int wt = gwarp; wt < NUM_WTILES; wt += TOTAL_WARPS) {
        const long long base4 = (long long)wt * WTILE_VEC4;
        const float4* __restrict__ p4 = (const float4*)preds + base4;
        const float4* __restrict__ t4 = (const float4*)targets + base4;

        // Front-batched loads: 75 float4 per tensor over 32 lanes.
        float4 pA, pB, pC, tA, tB, tC;
        pA = p4[lane];        tA = t4[lane];
        pB = p4[lane + 32];   tB = t4[lane + 32];
        const bool hasC = (lane < WTILE_VEC4 - 64);   // lanes 0..10
        if (hasC) { pC = p4[lane + 64]; tC = t4[lane + 64]; }

        __syncwarp();   // SMEM reuse guard: prior bone pass done before overwrite

        // Mask + L1 + SMEM store (fused).
        {
            float4 pm;
            pm.x = (tA.x != 0.0f) ? pA.x : 0.0f;
            pm.y = (tA.y != 0.0f) ? pA.y : 0.0f;
            pm.z = (tA.z != 0.0f) ? pA.z : 0.0f;
            pm.w = (tA.w != 0.0f) ? pA.w : 0.0f;
            l1 += fabsf(pm.x - tA.x) + fabsf(pm.y - tA.y)
                + fabsf(pm.z - tA.z) + fabsf(pm.w - tA.w);
            pm_s4[lane] = pm;  t_s4[lane] = tA;

            pm.x = (tB.x != 0.0f) ? pB.x : 0.0f;
            pm.y = (tB.y != 0.0f) ? pB.y : 0.0f;
            pm.z = (tB.z != 0.0f) ? pB.z : 0.0f;
            pm.w = (tB.w != 0.0f) ? pB.w : 0.0f;
            l1 += fabsf(pm.x - tB.x) + fabsf(pm.y - tB.y)
                + fabsf(pm.z - tB.z) + fabsf(pm.w - tB.w);
            pm_s4[lane + 32] = pm;  t_s4[lane + 32] = tB;

            if (hasC) {
                pm.x = (tC.x != 0.0f) ? pC.x : 0.0f;
                pm.y = (tC.y != 0.0f) ? pC.y : 0.0f;
                pm.z = (tC.z != 0.0f) ? pC.z : 0.0f;
                pm.w = (tC.w != 0.0f) ? pC.w : 0.0f;
                l1 += fabsf(pm.x - tC.x) + fabsf(pm.y - tC.y)
                    + fabsf(pm.z - tC.z) + fabsf(pm.w - tC.w);
                pm_s4[lane + 64] = pm;  t_s4[lane + 64] = tC;
            }
        }
        __syncwarp();

        // Bone pass: 2 rows * 50 bones = 100 tasks over 32 lanes.
        #pragma unroll
        for (int tk = 0; tk < 4; tk++) {
            int task = lane + tk * 32;
            if (task >= ROWS_PER_WTILE * N_BONES) break;
            int r = (task >= N_BONES) ? 1 : 0;
            int i = task - r * N_BONES;
            int j1 = (i + 1 == N_BONES) ? 0 : (i + 1);
            const float* __restrict__ pr = pm_s + r * ROW_ELEMS;
            const float* __restrict__ tr = t_s + r * ROW_ELEMS;

            float pdv[3], tdv[3], m[3];
            float pl2 = 0.0f, tl2 = 0.0f;
            #pragma unroll
            for (int d = 0; d < 3; d++) {
                float t0 = tr[i * 3 + d];
                float t1 = tr[j1 * 3 + d];
                float pdiff = pr[i * 3 + d] - pr[j1 * 3 + d];  // already masked
                float tdiff = t0 - t1;
                pdv[d] = pdiff;
                tdv[d] = tdiff;
                m[d] = (t0 != 0.0f) ? 1.0f : 0.0f;
                pl2 += pdiff * pdiff;
                tl2 += tdiff * tdiff;
            }
            // 1/(sqrt(x)+1e-8) ≈ rsqrt(x) to ~1e-8 rel; exact-0 guarded (ref -> 0).
            float pinv = (pl2 > 0.0f) ? rsqrtf(pl2) : 0.0f;
            float tinv = (tl2 > 0.0f) ? rsqrtf(tl2) : 0.0f;
            #pragma unroll
            for (int d = 0; d < 3; d++) {
                float x = (pdv[d] * pinv - tdv[d] * tinv) * m[d];
                mse += x * x;
            }
        }
    }

    // ---- deterministic block reduction ----
    __shared__ float s_l1[THREADS];
    __shared__ float s_mse[THREADS];
    s_l1[tid] = l1;
    s_mse[tid] = mse;
    __syncthreads();
    #pragma unroll
    for (int s = THREADS / 2; s > 0; s >>= 1) {
        if (tid < s) {
            s_l1[tid] += s_l1[tid + s];
            s_mse[tid] += s_mse[tid + s];
        }
        __syncthreads();
    }

    // ---- last-arriving block does the final reduction (fixed order) ----
    __shared__ bool s_last;
    if (tid == 0) {
        g_partials[blockIdx.x] = make_float2(s_l1[0], s_mse[0]);
        __threadfence();
        unsigned int v = atomicAdd(&g_count, 1u);
        s_last = (v == LAUNCH_BLOCKS - 1);
    }
    __syncthreads();

    if (s_last) {
        __shared__ double d_l1[THREADS];
        __shared__ double d_mse[THREADS];
        double a = 0.0, b = 0.0;
        #pragma unroll
        for (int k = tid; k < LAUNCH_BLOCKS; k += THREADS) {
            float2 v = __ldcg(&g_partials[k]);
            a += (double)v.x;
            b += (double)v.y;
        }
        d_l1[tid] = a;
        d_mse[tid] = b;
        __syncthreads();
        #pragma unroll
        for (int s = THREADS / 2; s > 0; s >>= 1) {
            if (tid < s) {
                d_l1[tid] += d_l1[tid + s];
                d_mse[tid] += d_mse[tid + s];
            }
            __syncthreads();
        }
        if (tid == 0) {
            const double TOT = (double)TOTAL_ROWS * (double)ROW_ELEMS;
            out[0] = (float)(d_l1[0] / TOT + 0.1 * (d_mse[0] / TOT));
            g_count = 0;   // reset for next graph replay
        }
    }
}

extern "C" void kernel_launch(void* const* d_in, const int* in_sizes, int n_in,
                              void* d_out, int out_size)
{
    const float* preds   = (const float*)d_in[0];
    const float* targets = (const float*)d_in[1];
    float* out = (float*)d_out;

    loss_fused<<<LAUNCH_BLOCKS, THREADS>>>(preds, targets, out);
}